// round 3
// baseline (speedup 1.0000x reference)
#include <cuda_runtime.h>
#include <cstddef>
#include <cstdint>

// Problem constants
#define BB   128     // batch
#define TT   512     // seq len
#define EE   256     // embed dim
#define HH   256     // hidden
#define G4H  1024    // 4*H
#define VV   32000   // vocab
#define NC   32      // classes

// ---------------- device scratch (no allocations allowed) ----------------
__device__ float g_P[(size_t)VV * 2048];     // [V][2*4H]  vocab projection (+bias folded)
__device__ float g_hT[2][2][HH][BB];         // [phase][dir][hcol][row]  transposed hidden, dbl-buffered
__device__ float g_hfinT[2][HH][BB];         // final hidden per direction, transposed
__device__ int   g_bar;                      // grid barrier counter

// ---------------- f32x2 helpers (FFMA2 path, PTX-only) ----------------
__device__ __forceinline__ unsigned long long pack2(float lo, float hi) {
    unsigned long long r;
    asm("mov.b64 %0, {%1, %2};" : "=l"(r) : "f"(lo), "f"(hi));
    return r;
}
__device__ __forceinline__ float2 unpack2(unsigned long long v) {
    float2 r;
    asm("mov.b64 {%0, %1}, %2;" : "=f"(r.x), "=f"(r.y) : "l"(v));
    return r;
}
__device__ __forceinline__ void ffma2(unsigned long long& d, unsigned long long a, unsigned long long b) {
    asm("fma.rn.f32x2 %0, %1, %2, %0;" : "+l"(d) : "l"(a), "l"(b));
}

__device__ __forceinline__ int ld_acq(const int* p) {
    int v;
    asm volatile("ld.acquire.gpu.b32 %0, [%1];" : "=r"(v) : "l"(p));
    return v;
}

__device__ __forceinline__ float sigm(float x) { return 1.0f / (1.0f + expf(-x)); }

__device__ __forceinline__ void cpasync16(uint32_t dst, const void* src) {
    asm volatile("cp.async.cg.shared.global [%0], [%1], 16;" :: "r"(dst), "l"(src) : "memory");
}
__device__ __forceinline__ void cp_commit() {
    asm volatile("cp.async.commit_group;" ::: "memory");
}
template<int N> __device__ __forceinline__ void cp_wait() {
    asm volatile("cp.async.wait_group %0;" :: "n"(N) : "memory");
}

__device__ __forceinline__ void gridbar(int target) {
    __syncthreads();
    if (threadIdx.x == 0) {
        __threadfence();
        atomicAdd(&g_bar, 1);
        while (ld_acq(&g_bar) < target) { }
    }
    __syncthreads();
}

// =====================================================================
// Kernel A: P[v, d*1024+g] = sum_e emb[v,e] * W{f,b}[e,g] + b{f,b}[g]
// (unchanged from round 2 — known correct; also resets g_bar)
// =====================================================================
__global__ void __launch_bounds__(256) proj_kernel(
    const float* __restrict__ emb,
    const float* __restrict__ Wf, const float* __restrict__ bf,
    const float* __restrict__ Wb, const float* __restrict__ bb)
{
    if (blockIdx.x == 0 && blockIdx.y == 0 && threadIdx.x == 0) g_bar = 0;

    __shared__ float As[16][68];
    __shared__ float Bs[16][64];

    const int tid = threadIdx.x;
    const int tx = tid & 15, ty = tid >> 4;
    const int m0 = ty * 4, n0 = tx * 4;
    const int vbase = blockIdx.y * 64;
    const int nbase = blockIdx.x * 64;
    const int d = nbase >> 10;
    const float* W    = d ? Wb : Wf;
    const float* bias = d ? bb : bf;
    const int gbase = nbase & 1023;

    unsigned long long acc[4][2] = {};

    for (int kt = 0; kt < 256; kt += 16) {
        #pragma unroll
        for (int i = tid; i < 1024; i += 256) {
            int row = i >> 4, k = i & 15;
            As[k][row] = emb[(size_t)(vbase + row) * EE + kt + k];
        }
        #pragma unroll
        for (int i = tid; i < 1024; i += 256) {
            int k = i >> 6, c = i & 63;
            Bs[k][c] = W[(size_t)(kt + k) * G4H + gbase + c];
        }
        __syncthreads();
        #pragma unroll
        for (int k = 0; k < 16; k++) {
            float4 a4 = *(const float4*)&As[k][m0];
            const unsigned long long* bp = (const unsigned long long*)&Bs[k][n0];
            unsigned long long b0 = bp[0], b1 = bp[1];
            #pragma unroll
            for (int i = 0; i < 4; i++) {
                float av = ((const float*)&a4)[i];
                unsigned long long ad = pack2(av, av);
                ffma2(acc[i][0], ad, b0);
                ffma2(acc[i][1], ad, b1);
            }
        }
        __syncthreads();
    }

    #pragma unroll
    for (int i = 0; i < 4; i++) {
        int v = vbase + m0 + i;
        #pragma unroll
        for (int p = 0; p < 2; p++) {
            float2 va = unpack2(acc[i][p]);
            int c = n0 + 2 * p;
            va.x += bias[gbase + c];
            va.y += bias[gbase + c + 1];
            *(float2*)&g_P[(size_t)v * 2048 + nbase + c] = va;
        }
    }
}

// =====================================================================
// Kernel B: persistent bidirectional LSTM recurrence (redesigned).
// 128 CTAs (64/dir) x 256 threads. CTA (d,s) owns h-cols j0=4s..4s+4.
// Thread: hc = tid&3 (h-col within CTA), rg = tid>>2 (row pair 2rg,2rg+1).
// Thread tile = 2 rows x 4 gates x 1 hcol; f32x2 packed over the row pair.
// U pre-duplicated in SMEM as (u,u) ull pairs -> no pack movs in the loop.
// h exchanged via global (transposed layout) with cp.async 4-chunk pipeline.
// =====================================================================
#define LSTM_SMEM_BYTES (4096 * 8 + 32768 * 4)   // UsD (32KB) + hs (128KB) = 160KB

template<int C, int WG>
__device__ __forceinline__ void lstm_chunk(
    const float* hs, const unsigned long long* UsD, int hc, int r0,
    unsigned long long& a0, unsigned long long& a1,
    unsigned long long& a2, unsigned long long& a3)
{
    cp_wait<WG>();
    __syncthreads();
    #pragma unroll 8
    for (int k = C * 64; k < C * 64 + 64; k++) {
        unsigned long long hp = *(const unsigned long long*)(hs + k * 128 + r0);
        const unsigned long long* up = UsD + k * 16 + hc * 4;
        ulonglong2 u01 = *(const ulonglong2*)up;
        ulonglong2 u23 = *(const ulonglong2*)(up + 2);
        ffma2(a0, hp, u01.x);
        ffma2(a1, hp, u01.y);
        ffma2(a2, hp, u23.x);
        ffma2(a3, hp, u23.y);
    }
}

__global__ void __launch_bounds__(256) lstm_kernel(
    const int* __restrict__ tokens,
    const float* __restrict__ Uf, const float* __restrict__ Ub)
{
    extern __shared__ char smem_raw[];
    unsigned long long* UsD = (unsigned long long*)smem_raw;        // [256][4 hc][4 g] dup'd
    float* hs = (float*)(smem_raw + 4096 * 8);                      // [256 hcol][128 row]
    const uint32_t hs_addr = (uint32_t)__cvta_generic_to_shared(hs);

    const int tid = threadIdx.x;
    const int d  = blockIdx.x >> 6;
    const int s  = blockIdx.x & 63;
    const int j0 = s * 4;
    const float* U = d ? Ub : Uf;

    // Token dtype guard (jnp.int64 usually silently x32 in JAX).
    const bool is64 = ((tokens[1] | tokens[3] | tokens[5] | tokens[7]) == 0);
    const int ts = is64 ? 2 : 1;

    // Preload duplicated U tile: UsD[k*16 + hc*4 + g] = dup(U[k][g*256 + j0 + hc])
    for (int i = tid; i < 4096; i += 256) {
        int k = i >> 4, cc = i & 15;
        int hcx = cc >> 2, g = cc & 3;
        float v = U[(size_t)k * G4H + g * 256 + j0 + hcx];
        UsD[i] = pack2(v, v);
    }

    const int hc = tid & 3;
    const int rg = tid >> 2;          // 0..63
    const int r0 = rg * 2;

    // zero-init phase-0 hidden: this CTA's 4 hcols, all 128 rows
    for (int i = tid; i < 512; i += 256) {
        int hh = i >> 7, rr = i & 127;
        g_hT[0][d][j0 + hh][rr] = 0.f;
    }
    float c0 = 0.f, c1 = 0.f;

    int target = 128;
    gridbar(target);    // zeros + U tiles visible everywhere

    const size_t trow0 = (size_t)r0 * TT * ts;
    const size_t trow1 = (size_t)(r0 + 1) * TT * ts;

    for (int t = 0; t < TT; t++) {
        const int p = t & 1;
        const int te = d ? (TT - 1 - t) : t;

        // issue staged copy of h (128 KB) in 4 committed chunks
        const float4* src = (const float4*)&g_hT[p][d][0][0];
        #pragma unroll
        for (int c = 0; c < 4; c++) {
            #pragma unroll
            for (int i = 0; i < 8; i++) {
                int f = tid + 256 * (c * 8 + i);
                cpasync16(hs_addr + f * 16, src + f);
            }
            cp_commit();
        }

        // tokens + input-projection rows (DRAM latency hidden behind k-loop)
        int t0 = tokens[trow0 + (size_t)te * ts]; t0 = (t0 >= 0 && t0 < VV) ? t0 : 0;
        int t1 = tokens[trow1 + (size_t)te * ts]; t1 = (t1 >= 0 && t1 < VV) ? t1 : 0;
        const float* P0 = g_P + (size_t)t0 * 2048 + d * 1024 + j0 + hc;
        const float* P1 = g_P + (size_t)t1 * 2048 + d * 1024 + j0 + hc;
        float p00 = P0[0], p01 = P0[256], p02 = P0[512], p03 = P0[768];
        float p10 = P1[0], p11 = P1[256], p12 = P1[512], p13 = P1[768];

        unsigned long long a0 = 0, a1 = 0, a2 = 0, a3 = 0;
        lstm_chunk<0, 3>(hs, UsD, hc, r0, a0, a1, a2, a3);
        lstm_chunk<1, 2>(hs, UsD, hc, r0, a0, a1, a2, a3);
        lstm_chunk<2, 1>(hs, UsD, hc, r0, a0, a1, a2, a3);
        lstm_chunk<3, 0>(hs, UsD, hc, r0, a0, a1, a2, a3);

        float2 zi = unpack2(a0), zf = unpack2(a1), zg = unpack2(a2), zo = unpack2(a3);
        zi.x += p00; zi.y += p10;
        zf.x += p01; zf.y += p11;
        zg.x += p02; zg.y += p12;
        zo.x += p03; zo.y += p13;

        float i0 = sigm(zi.x), i1 = sigm(zi.y);
        float f0 = sigm(zf.x), f1 = sigm(zf.y);
        float gg0 = tanhf(zg.x), gg1 = tanhf(zg.y);
        float o0 = sigm(zo.x), o1 = sigm(zo.y);
        c0 = f0 * c0 + i0 * gg0;
        c1 = f1 * c1 + i1 * gg1;
        float h0 = o0 * tanhf(c0);
        float h1 = o1 * tanhf(c1);

        if (t == TT - 1) {
            *(float2*)&g_hfinT[d][j0 + hc][r0] = make_float2(h0, h1);
        } else {
            *(float2*)&g_hT[p ^ 1][d][j0 + hc][r0] = make_float2(h0, h1);
            target += 128;
            gridbar(target);
        }
    }
}

// =====================================================================
// Kernel C: head.  h1 = relu([hf|hb] @ W1 + b1); out = softmax(h1 @ W2 + b2)
// =====================================================================
__global__ void __launch_bounds__(256) head_kernel(
    const float* __restrict__ W1, const float* __restrict__ b1,
    const float* __restrict__ W2, const float* __restrict__ b2,
    float* __restrict__ out)
{
    __shared__ float hc[8][512];
    __shared__ float h1[8][256];

    const int tid = threadIdx.x;
    const int rb = blockIdx.x * 8;

    for (int i = tid; i < 4096; i += 256) {
        int rr = i >> 9, k = i & 511;
        int dd = k >> 8, kk = k & 255;
        hc[rr][k] = g_hfinT[dd][kk][rb + rr];
    }
    __syncthreads();

    const int j = tid;
    float acc[8] = {0.f, 0.f, 0.f, 0.f, 0.f, 0.f, 0.f, 0.f};
    for (int k = 0; k < 512; k++) {
        float w = W1[(size_t)k * HH + j];
        #pragma unroll
        for (int rr = 0; rr < 8; rr++) acc[rr] += hc[rr][k] * w;
    }
    float bj = b1[j];
    #pragma unroll
    for (int rr = 0; rr < 8; rr++) h1[rr][j] = fmaxf(acc[rr] + bj, 0.f);
    __syncthreads();

    const int rr = tid >> 5, c = tid & 31;
    float l = b2[c];
    for (int k = 0; k < HH; k++) l += h1[rr][k] * W2[(size_t)k * NC + c];

    float m = l;
    #pragma unroll
    for (int o = 16; o > 0; o >>= 1) m = fmaxf(m, __shfl_xor_sync(0xffffffffu, m, o));
    float e = expf(l - m);
    float ssum = e;
    #pragma unroll
    for (int o = 16; o > 0; o >>= 1) ssum += __shfl_xor_sync(0xffffffffu, ssum, o);
    out[(size_t)(rb + rr) * NC + c] = e / ssum;
}

// =====================================================================
extern "C" void kernel_launch(void* const* d_in, const int* in_sizes, int n_in,
                              void* d_out, int out_size)
{
    const int*   tokens = (const int*)d_in[0];
    const float* emb = (const float*)d_in[1];
    const float* Wf  = (const float*)d_in[2];
    const float* Uf  = (const float*)d_in[3];
    const float* bf  = (const float*)d_in[4];
    const float* Wb  = (const float*)d_in[5];
    const float* Ub  = (const float*)d_in[6];
    const float* bb  = (const float*)d_in[7];
    const float* W1  = (const float*)d_in[8];
    const float* b1  = (const float*)d_in[9];
    const float* W2  = (const float*)d_in[10];
    const float* b2  = (const float*)d_in[11];
    float* out = (float*)d_out;

    cudaFuncSetAttribute(lstm_kernel, cudaFuncAttributeMaxDynamicSharedMemorySize, LSTM_SMEM_BYTES);

    proj_kernel<<<dim3(32, 500), 256>>>(emb, Wf, bf, Wb, bb);
    lstm_kernel<<<128, 256, LSTM_SMEM_BYTES>>>(tokens, Uf, Ub);
    head_kernel<<<16, 256>>>(W1, b1, W2, b2, out);
}